// round 1
// baseline (speedup 1.0000x reference)
#include <cuda_runtime.h>
#include <cstdint>

// Problem-fixed shapes (QuantizedKVCache_52381421142177):
//   k_val/v_val : (1, 128, 32, 128)  f32
//   k_cache/v_cache : (1, 8192, 32, 128) i32
//   k_scales/v_scales : (1, 8192, 32, 1) f32
//   k_zp/v_zp : (1, 8192, 32, 1) i32
//   input_pos : scalar i32
// Output: concat(k_out, v_out), each (1, 8192, 32, 128) f32.
//
// Output semantics (quantization of fresh tokens is dead code w.r.t. output):
//   s in [pos, pos+S_NEW):  out = val (exact fp copy)
//   else:                   out = (cache - zp) * scale

static constexpr int S_MAX = 8192;
static constexpr int H     = 32;    // heads  (power of 2 -> shift)
static constexpr int D4    = 32;    // D/4 = 128/4 vec4 per token (power of 2)
static constexpr int S_NEW = 128;
static constexpr long long CACHE_V4 = (long long)S_MAX * H * D4;  // 8,388,608 vec4 per cache

__global__ void __launch_bounds__(256)
qkv_dequant_kernel(const float4* __restrict__ k_val,
                   const float4* __restrict__ v_val,
                   const int4*  __restrict__ k_cache,
                   const int4*  __restrict__ v_cache,
                   const float* __restrict__ k_scales,
                   const float* __restrict__ v_scales,
                   const int*   __restrict__ k_zp,
                   const int*   __restrict__ v_zp,
                   const int*   __restrict__ pos_ptr,
                   float4*      __restrict__ out)
{
    const int pos = *pos_ptr;                      // L1-broadcast scalar
    const long long total = 2LL * CACHE_V4;
    const long long stride = (long long)gridDim.x * blockDim.x;

    for (long long i = (long long)blockIdx.x * blockDim.x + threadIdx.x;
         i < total; i += stride) {

        const bool is_v = (i >= CACHE_V4);
        const long long j = is_v ? (i - CACHE_V4) : i;   // vec4 index within one cache
        const long long t = j >> 5;                      // token index = j / D4
        const int s = (int)(t >> 5);                     // seq index  = t / H  (B=1)
        const int sl = s - pos;

        float4 r;
        if ((unsigned)sl < (unsigned)S_NEW) {
            // fresh token: exact copy from val
            const long long vt = ((long long)sl << 5) + (t & (H - 1));  // sl*H + h
            const float4* val = is_v ? v_val : k_val;
            r = val[(vt << 5) + (j & (D4 - 1))];
        } else {
            // stale token: dequantize
            const int4 q = (is_v ? v_cache : k_cache)[j];
            const float sc = (is_v ? v_scales : k_scales)[t];
            const float zp = (float)((is_v ? v_zp : k_zp)[t]);
            r.x = ((float)q.x - zp) * sc;
            r.y = ((float)q.y - zp) * sc;
            r.z = ((float)q.z - zp) * sc;
            r.w = ((float)q.w - zp) * sc;
        }
        out[i] = r;
    }
}

extern "C" void kernel_launch(void* const* d_in, const int* in_sizes, int n_in,
                              void* d_out, int out_size)
{
    const float4* k_val    = (const float4*)d_in[0];
    const float4* v_val    = (const float4*)d_in[1];
    const int4*   k_cache  = (const int4*)d_in[2];
    const int4*   v_cache  = (const int4*)d_in[3];
    const float*  k_scales = (const float*)d_in[4];
    const float*  v_scales = (const float*)d_in[5];
    const int*    k_zp     = (const int*)d_in[6];
    const int*    v_zp     = (const int*)d_in[7];
    const int*    pos_ptr  = (const int*)d_in[8];

    const long long total = 2LL * CACHE_V4;     // 16,777,216 vec4
    const int threads = 256;
    const int blocks = (int)((total + threads - 1) / threads);  // 65,536

    qkv_dequant_kernel<<<blocks, threads>>>(
        k_val, v_val, k_cache, v_cache,
        k_scales, v_scales, k_zp, v_zp,
        pos_ptr, (float4*)d_out);
}

// round 2
// speedup vs baseline: 1.1132x; 1.1132x over previous
#include <cuda_runtime.h>
#include <cstdint>

// QuantizedKVCache_52381421142177 — fixed shapes:
//   k_val/v_val   : (1, 128, 32, 128)  f32
//   k_cache/v_cache: (1, 8192, 32, 128) i32
//   k_scales/v_scales: (1, 8192, 32, 1) f32
//   k_zp/v_zp     : (1, 8192, 32, 1) i32
//   input_pos     : scalar i32
// Output: concat(k_out, v_out), each (1, 8192, 32, 128) f32.
//
// Output semantics (fresh-token quantization is dead code w.r.t. output):
//   s in [pos, pos+128):  out = val (exact fp copy)
//   else:                 out = (cache - zp) * scale
//
// Layout trick: one seq position = 32 heads * 32 vec4 = 1024 vec4
//             = one block of 256 threads * 4 vec4/thread.
// -> fresh/stale branch is block-uniform; all indexing is 32-bit shifts.

static constexpr int S_MAX   = 8192;
static constexpr int S_NEW   = 128;
static constexpr int V4_PER_S = 1024;          // 32 heads * 32 vec4
static constexpr int T_PER_S  = 32;            // tokens (head rows) per seq pos

__global__ void __launch_bounds__(256)
qkv_dequant_kernel(const float4* __restrict__ k_val,
                   const float4* __restrict__ v_val,
                   const int4*   __restrict__ k_cache,
                   const int4*   __restrict__ v_cache,
                   const float*  __restrict__ k_scales,
                   const float*  __restrict__ v_scales,
                   const int*    __restrict__ k_zp,
                   const int*    __restrict__ v_zp,
                   const int*    __restrict__ pos_ptr,
                   float4*       __restrict__ out)
{
    const unsigned bid  = blockIdx.x;            // [0, 16384)
    const unsigned is_v = bid >> 13;             // 0 = K, 1 = V (uniform)
    const unsigned s    = bid & (S_MAX - 1);     // seq position (uniform)
    const unsigned tid  = threadIdx.x;

    const unsigned pos = (unsigned)*pos_ptr;
    const unsigned sl  = s - pos;                // fresh iff sl < S_NEW

    // base vec4 index of this seq position within one cache
    const unsigned jbase = s * V4_PER_S;
    // output base (V half offset = 8,388,608 vec4)
    float4* dst = out + (size_t)is_v * ((size_t)S_MAX * V4_PER_S) + jbase;

    if (sl < (unsigned)S_NEW) {
        // ---- fresh token block: exact fp copy from val ----
        const float4* val = (is_v ? v_val : k_val) + (size_t)sl * V4_PER_S;
        #pragma unroll
        for (int k = 0; k < 4; k++) {
            const unsigned e = k * 256 + tid;
            __stcs(dst + e, __ldcs(val + e));
        }
    } else {
        // ---- stale block: dequantize ----
        const int4*  cache  = (is_v ? v_cache  : k_cache)  + jbase;
        const float* scales = (is_v ? v_scales : k_scales) + s * T_PER_S;
        const int*   zps    = (is_v ? v_zp     : k_zp)     + s * T_PER_S;

        int4  q[4];
        float sc[4], zp[4];
        #pragma unroll
        for (int k = 0; k < 4; k++) {            // front-batched loads: MLP=4
            const unsigned e = k * 256 + tid;
            q[k]  = __ldcs(cache + e);
            const unsigned trow = e >> 5;        // token row within this s
            sc[k] = __ldg(scales + trow);
            zp[k] = (float)__ldg(zps + trow);
        }
        #pragma unroll
        for (int k = 0; k < 4; k++) {
            const unsigned e = k * 256 + tid;
            float4 r;
            r.x = ((float)q[k].x - zp[k]) * sc[k];
            r.y = ((float)q[k].y - zp[k]) * sc[k];
            r.z = ((float)q[k].z - zp[k]) * sc[k];
            r.w = ((float)q[k].w - zp[k]) * sc[k];
            __stcs(dst + e, r);
        }
    }
}

extern "C" void kernel_launch(void* const* d_in, const int* in_sizes, int n_in,
                              void* d_out, int out_size)
{
    const float4* k_val    = (const float4*)d_in[0];
    const float4* v_val    = (const float4*)d_in[1];
    const int4*   k_cache  = (const int4*)d_in[2];
    const int4*   v_cache  = (const int4*)d_in[3];
    const float*  k_scales = (const float*)d_in[4];
    const float*  v_scales = (const float*)d_in[5];
    const int*    k_zp     = (const int*)d_in[6];
    const int*    v_zp     = (const int*)d_in[7];
    const int*    pos_ptr  = (const int*)d_in[8];

    // 2 caches * 8192 seq positions, one block per (cache, s)
    qkv_dequant_kernel<<<2 * S_MAX, 256>>>(
        k_val, v_val, k_cache, v_cache,
        k_scales, v_scales, k_zp, v_zp,
        pos_ptr, (float4*)d_out);
}